// round 3
// baseline (speedup 1.0000x reference)
#include <cuda_runtime.h>

#define DIM     128
#define NCLS    50
#define PAIRS   25
#define WPITCH  384
#define PPITCH  64          // floats per P/Q row (256B, 16B-aligned)
#define NMAX    50000
#define WROW    26          // packed pairs per k-row (25 + pad), 208B
#define ECHUNK  32          // k-chunk of e staged in smem
#define EPITCH  36          // floats per staged e-row (32 + 4 pad)
#define EBT     256         // edge-kernel block threads (= edges per block)

typedef unsigned long long ull;

__device__ float g_P[NMAX * PPITCH];
__device__ float g_Q[NMAX * PPITCH];
__device__ int   g_idx64;

// ---- packed f32x2 helpers ----------------------------------------------
__device__ __forceinline__ ull fma2(ull a, ull b, ull c) {
    ull d;
    asm("fma.rn.f32x2 %0, %1, %2, %3;" : "=l"(d) : "l"(a), "l"(b), "l"(c));
    return d;
}
__device__ __forceinline__ ull add2(ull a, ull b) {
    ull d;
    asm("add.rn.f32x2 %0, %1, %2;" : "=l"(d) : "l"(a), "l"(b));
    return d;
}
__device__ __forceinline__ ull dup2(float x) {
    ull d; unsigned int u = __float_as_uint(x);
    asm("mov.b64 %0, {%1, %1};" : "=l"(d) : "r"(u));
    return d;
}

// --------------------------------------------------------------------------
// Node kernel: P[n] = h[n]·W1^T + b,  Q[n] = h[n]·W2^T  (both in one pass).
// Thread 0 of block 0 also detects int64-vs-int32 index width.
// --------------------------------------------------------------------------
__global__ __launch_bounds__(256)
void node_kernel(const float* __restrict__ h,
                 const float* __restrict__ W,
                 const float* __restrict__ b,
                 const void*  __restrict__ src,
                 int N, int E)
{
    __shared__ float2 wS[2 * DIM * WROW];   // [half][k][pair], 53.2 KB

    if (blockIdx.x == 0 && threadIdx.x == 0) {
        const unsigned int* a = (const unsigned int*)src;
        int n = E < 256 ? E : 256;
        int all_hi_zero = 1;
        for (int i = 0; i < n; i++)
            if (a[2 * i + 1] != 0u) { all_hi_zero = 0; break; }
        g_idx64 = all_hi_zero;
    }

    for (int i = threadIdx.x; i < 2 * DIM * PAIRS; i += blockDim.x) {
        int half = i / (DIM * PAIRS);
        int r = i % (DIM * PAIRS);
        int k = r / PAIRS, c = r % PAIRS;
        wS[half * DIM * WROW + k * WROW + c] =
            make_float2(W[(2 * c) * WPITCH + half * DIM + k],
                        W[(2 * c + 1) * WPITCH + half * DIM + k]);
    }
    __syncthreads();

    int nid = blockIdx.x * blockDim.x + threadIdx.x;
    if (nid >= N) return;

    ull accP[PAIRS], accQ[PAIRS];
    const ull* b2 = (const ull*)b;
#pragma unroll
    for (int c = 0; c < PAIRS; c++) { accP[c] = b2[c]; accQ[c] = 0ull; }

    const float4* hr = (const float4*)(h + (size_t)nid * DIM);

#pragma unroll 1
    for (int kc = 0; kc < DIM / 4; kc++) {
        float4 f = hr[kc];
        float fs[4] = {f.x, f.y, f.z, f.w};
#pragma unroll
        for (int kk = 0; kk < 4; kk++) {
            int k = kc * 4 + kk;
            ull a = dup2(fs[kk]);
            const ull* w1 = (const ull*)&wS[k * WROW];
            const ull* w2 = (const ull*)&wS[DIM * WROW + k * WROW];
#pragma unroll
            for (int c = 0; c < PAIRS; c++) {
                accP[c] = fma2(a, w1[c], accP[c]);
                accQ[c] = fma2(a, w2[c], accQ[c]);
            }
        }
    }

    ull* dp = (ull*)(g_P + (size_t)nid * PPITCH);
    ull* dq = (ull*)(g_Q + (size_t)nid * PPITCH);
#pragma unroll
    for (int c = 0; c < PAIRS; c++) { dp[c] = accP[c]; dq[c] = accQ[c]; }
}

// --------------------------------------------------------------------------
// Edge kernel: block handles EBT consecutive edges; e-rows staged via smem
// in K-chunks with coalesced global reads; W3 broadcast from smem;
// P/Q gathered and output stored with float4-wide accesses.
// --------------------------------------------------------------------------
__global__ __launch_bounds__(EBT)
void edge_kernel(const float* __restrict__ efeat,
                 const void*  __restrict__ src,
                 const void*  __restrict__ dst,
                 const float* __restrict__ W,
                 float* __restrict__ out,
                 int E)
{
    __shared__ float2 wp[DIM * WROW];           // W3 packed, 26.6 KB
    __shared__ float  eS[EBT * EPITCH];         // e chunk, 36.9 KB

    const int tid = threadIdx.x;

    for (int i = tid; i < DIM * PAIRS; i += EBT) {
        int k = i / PAIRS, c = i % PAIRS;
        wp[k * WROW + c] = make_float2(W[(2 * c) * WPITCH + 2 * DIM + k],
                                       W[(2 * c + 1) * WPITCH + 2 * DIM + k]);
    }

    const long long base = (long long)blockIdx.x * EBT;
    const long long eid  = base + tid;
    const bool valid = (eid < E);
    const long long eidc = valid ? eid : (long long)(E - 1);

    long long s, d;
    if (g_idx64) {
        s = ((const long long*)src)[eidc];
        d = ((const long long*)dst)[eidc];
    } else {
        s = ((const int*)src)[eidc];
        d = ((const int*)dst)[eidc];
    }

    // gather P[s] + Q[d] with 16B loads (rows are 256B-aligned)
    ull acc[PAIRS];
    {
        const ulonglong2* pr = (const ulonglong2*)(g_P + (size_t)s * PPITCH);
        const ulonglong2* qr = (const ulonglong2*)(g_Q + (size_t)d * PPITCH);
#pragma unroll
        for (int j = 0; j < 12; j++) {
            ulonglong2 p = pr[j];
            ulonglong2 q = qr[j];
            acc[2 * j]     = add2(p.x, q.x);
            acc[2 * j + 1] = add2(p.y, q.y);
        }
        acc[24] = add2(((const ull*)pr)[24], ((const ull*)qr)[24]);
    }

    __syncthreads();   // wp ready

    const float* myrow = eS + tid * EPITCH;

#pragma unroll 1
    for (int ch = 0; ch < DIM / ECHUNK; ch++) {
        // stage: 256 rows x 32 floats, coalesced float4 reads
#pragma unroll
        for (int i = 0; i < (EBT * ECHUNK / 4) / EBT; i++) {    // 8 iters
            int idx = i * EBT + tid;
            int r = idx >> 3;            // row 0..255
            int c4 = idx & 7;            // float4 col 0..7
            long long grow = base + r;
            if (grow >= E) grow = E - 1;
            float4 v = *(const float4*)(efeat + (size_t)grow * DIM + ch * ECHUNK + c4 * 4);
            *(float4*)(eS + r * EPITCH + c4 * 4) = v;
        }
        __syncthreads();

#pragma unroll
        for (int kk = 0; kk < ECHUNK / 4; kk++) {
            float4 f = *(const float4*)(myrow + kk * 4);
            float fs[4] = {f.x, f.y, f.z, f.w};
#pragma unroll
            for (int q = 0; q < 4; q++) {
                int k = ch * ECHUNK + kk * 4 + q;
                ull a = dup2(fs[q]);
                const ulonglong2* wrow = (const ulonglong2*)&wp[k * WROW];
#pragma unroll
                for (int j = 0; j < 12; j++) {
                    ulonglong2 w = wrow[j];
                    acc[2 * j]     = fma2(a, w.x, acc[2 * j]);
                    acc[2 * j + 1] = fma2(a, w.y, acc[2 * j + 1]);
                }
                acc[24] = fma2(a, ((const ull*)wrow)[24], acc[24]);
            }
        }
        __syncthreads();
    }

    if (valid) {
        float* orow = out + (size_t)eid * NCLS;   // 200B rows: parity alignment
        if ((eid & 1) == 0) {
            ulonglong2* o = (ulonglong2*)orow;    // 16B-aligned
#pragma unroll
            for (int j = 0; j < 12; j++)
                o[j] = make_ulonglong2(acc[2 * j], acc[2 * j + 1]);
            ((ull*)orow)[24] = acc[24];
        } else {
            ((ull*)orow)[0] = acc[0];             // 8B head
            ulonglong2* o = (ulonglong2*)(orow + 2);  // now 16B-aligned
#pragma unroll
            for (int j = 0; j < 12; j++)
                o[j] = make_ulonglong2(acc[2 * j + 1], acc[2 * j + 2]);
        }
    }
}

// --------------------------------------------------------------------------
extern "C" void kernel_launch(void* const* d_in, const int* in_sizes, int n_in,
                              void* d_out, int out_size)
{
    const float* h   = (const float*)d_in[0];
    const float* e   = (const float*)d_in[1];
    const void*  src = d_in[2];
    const void*  dst = d_in[3];
    const float* W   = (const float*)d_in[4];
    const float* b   = (const float*)d_in[5];

    int N = in_sizes[0] / DIM;   // 50000
    int E = in_sizes[1] / DIM;   // 500000
    if (N > NMAX) N = NMAX;

    node_kernel<<<(N + 255) / 256, 256>>>(h, W, b, src, N, E);
    edge_kernel<<<(E + EBT - 1) / EBT, EBT>>>(e, src, dst, W, (float*)d_out, E);
}

// round 4
// speedup vs baseline: 1.2876x; 1.2876x over previous
#include <cuda_runtime.h>

#define DIM     128
#define NCLS    50
#define PAIRS   25
#define WPITCH  384
#define PPITCH  64          // floats per P/Q row (256B)
#define NMAX    50000
#define WROW    26          // float2 slots per k-row of packed W

typedef unsigned long long ull;

__device__ float g_P[NMAX * PPITCH];
__device__ float g_Q[NMAX * PPITCH];
__device__ int   g_idx64;

// ---- packed f32x2 helpers ----------------------------------------------
__device__ __forceinline__ ull fma2(ull a, ull b, ull c) {
    ull d;
    asm("fma.rn.f32x2 %0, %1, %2, %3;" : "=l"(d) : "l"(a), "l"(b), "l"(c));
    return d;
}
__device__ __forceinline__ ull add2(ull a, ull b) {
    ull d;
    asm("add.rn.f32x2 %0, %1, %2;" : "=l"(d) : "l"(a), "l"(b));
    return d;
}
__device__ __forceinline__ ull dup2(float x) {
    ull d; unsigned int u = __float_as_uint(x);
    asm("mov.b64 %0, {%1, %1};" : "=l"(d) : "r"(u));
    return d;
}
__device__ __forceinline__ float f4get(const float4& f, int q) {
    return q == 0 ? f.x : (q == 1 ? f.y : (q == 2 ? f.z : f.w));
}

// ==========================================================================
// Node kernel: P[n] = h[n]*W1^T + b,  Q[n] = h[n]*W2^T  (one pass).
// 128 threads, 1 node/thread, h staged transposed through smem.
// smem: wS 53248 + hS 16512 = 69760 B (dynamic)
// ==========================================================================
#define NODE_SMEM 69760

__global__ __launch_bounds__(128, 3)
void node_kernel(const float* __restrict__ h,
                 const float* __restrict__ W,
                 const float* __restrict__ b,
                 const void*  __restrict__ src,
                 int N, int E)
{
    extern __shared__ __align__(16) char smem_n[];
    float2* wS  = (float2*)smem_n;                 // [2][128][26]
    float4* hS4 = (float4*)(smem_n + 53248);       // [8][129]

    const int tid = threadIdx.x;

    if (blockIdx.x == 0 && tid == 0) {
        const unsigned int* a = (const unsigned int*)src;
        int n = E < 256 ? E : 256;
        int all_hi_zero = 1;
        for (int i = 0; i < n; i++)
            if (a[2 * i + 1] != 0u) { all_hi_zero = 0; break; }
        g_idx64 = all_hi_zero;
    }

    for (int i = tid; i < 2 * DIM * PAIRS; i += 128) {
        int half = i / (DIM * PAIRS);
        int r = i % (DIM * PAIRS);
        int k = r / PAIRS, c = r % PAIRS;
        wS[half * DIM * WROW + k * WROW + c] =
            make_float2(W[(2 * c) * WPITCH + half * DIM + k],
                        W[(2 * c + 1) * WPITCH + half * DIM + k]);
    }

    const int base = blockIdx.x * 128;
    const int nid  = base + tid;

    ull accP[PAIRS], accQ[PAIRS];
    const ull* b2 = (const ull*)b;
#pragma unroll
    for (int c = 0; c < PAIRS; c++) { accP[c] = b2[c]; accQ[c] = 0ull; }

#pragma unroll 1
    for (int ch = 0; ch < 4; ch++) {
        __syncthreads();
        // stage 128 nodes x 32 k (8 float4), transposed [kg][node]
#pragma unroll
        for (int i = 0; i < 8; i++) {
            int idx = i * 128 + tid;
            int nd = idx >> 3, kg = idx & 7;
            int gn = base + nd; if (gn >= N) gn = N - 1;
            float4 v = *(const float4*)(h + (size_t)gn * DIM + ch * 32 + kg * 4);
            hS4[kg * 129 + nd] = v;
        }
        __syncthreads();

#pragma unroll 1
        for (int kg = 0; kg < 8; kg++) {
            float4 f = hS4[kg * 129 + tid];
#pragma unroll
            for (int q = 0; q < 4; q++) {
                int k = ch * 32 + kg * 4 + q;
                ull a = dup2(f4get(f, q));
                const ull* w1 = (const ull*)(wS + k * WROW);
#pragma unroll
                for (int c = 0; c < PAIRS; c++) accP[c] = fma2(a, w1[c], accP[c]);
                const ull* w2 = (const ull*)(wS + DIM * WROW + k * WROW);
#pragma unroll
                for (int c = 0; c < PAIRS; c++) accQ[c] = fma2(a, w2[c], accQ[c]);
            }
        }
    }

    if (nid < N) {
        ulonglong2* dp = (ulonglong2*)(g_P + (size_t)nid * PPITCH);
        ulonglong2* dq = (ulonglong2*)(g_Q + (size_t)nid * PPITCH);
#pragma unroll
        for (int j = 0; j < 12; j++) {
            dp[j] = make_ulonglong2(accP[2 * j], accP[2 * j + 1]);
            dq[j] = make_ulonglong2(accQ[2 * j], accQ[2 * j + 1]);
        }
        ((ull*)dp)[24] = accP[24];
        ((ull*)dq)[24] = accQ[24];
    }
}

// ==========================================================================
// Edge kernel: 128 threads, 256 edges/block (2 per thread: t and t+128).
// k-loop computes R = e_row · W3^T only; epilogue fuses P/Q gather + add +
// coalesced store through smem.
// smem: wp 26624 + sS 1024 + sD 1024 + scratch 32896 = 61568 B (dynamic)
// ==========================================================================
#define EDGE_SMEM 61568

__global__ __launch_bounds__(128, 3)
void edge_kernel(const float* __restrict__ efeat,
                 const void*  __restrict__ src,
                 const void*  __restrict__ dst,
                 const float* __restrict__ W,
                 float* __restrict__ out,
                 int E)
{
    extern __shared__ __align__(16) char smem_e[];
    float2* wp  = (float2*)smem_e;                 // [128][26]
    int*    sS  = (int*)(smem_e + 26624);          // [256]
    int*    sD  = (int*)(smem_e + 27648);          // [256]
    char*   scr = smem_e + 28672;                  // eS [8][257] f4 / sOut
    float4* eS4 = (float4*)scr;

    const int tid  = threadIdx.x;
    const int base = blockIdx.x * 256;
    const int use64 = g_idx64;

    for (int i = tid; i < DIM * PAIRS; i += 128) {
        int k = i / PAIRS, c = i % PAIRS;
        wp[k * WROW + c] = make_float2(W[(2 * c) * WPITCH + 2 * DIM + k],
                                       W[(2 * c + 1) * WPITCH + 2 * DIM + k]);
    }
    for (int i = tid; i < 256; i += 128) {
        long long g = base + i; if (g >= E) g = E - 1;
        int s, d;
        if (use64) {
            s = (int)((const long long*)src)[g];
            d = (int)((const long long*)dst)[g];
        } else {
            s = ((const int*)src)[g];
            d = ((const int*)dst)[g];
        }
        sS[i] = s; sD[i] = d;
    }

    ull accA[PAIRS], accB[PAIRS];
#pragma unroll
    for (int c = 0; c < PAIRS; c++) { accA[c] = 0ull; accB[c] = 0ull; }

#pragma unroll 1
    for (int ch = 0; ch < 4; ch++) {
        __syncthreads();
        // stage 256 edges x 32 k, transposed [kg][edge]
#pragma unroll
        for (int i = 0; i < 16; i++) {
            int idx = i * 128 + tid;
            int eL = idx >> 3, kg = idx & 7;
            int ge = base + eL; if (ge >= E) ge = E - 1;
            float4 v = *(const float4*)(efeat + (size_t)ge * DIM + ch * 32 + kg * 4);
            eS4[kg * 257 + eL] = v;
        }
        __syncthreads();

#pragma unroll 1
        for (int kg = 0; kg < 8; kg++) {
            float4 fa = eS4[kg * 257 + tid];
            float4 fb = eS4[kg * 257 + tid + 128];
#pragma unroll
            for (int q = 0; q < 4; q++) {
                int k = ch * 32 + kg * 4 + q;
                ull a0 = dup2(f4get(fa, q));
                ull a1 = dup2(f4get(fb, q));
                const ull* wr = (const ull*)(wp + k * WROW);
#pragma unroll
                for (int c = 0; c < PAIRS; c++) {
                    ull w = wr[c];
                    accA[c] = fma2(a0, w, accA[c]);
                    accB[c] = fma2(a1, w, accB[c]);
                }
            }
        }
    }

    // ---- epilogue: two half-passes of 128 rows each -----------------------
    ull* sOut = (ull*)scr;   // [128][25] ull = 25600 B (eS dead)

#pragma unroll 1
    for (int hf = 0; hf < 2; hf++) {
        __syncthreads();
        const ull* myacc = (hf == 0) ? accA : accB;
#pragma unroll
        for (int c = 0; c < PAIRS; c++) sOut[tid * PAIRS + c] = myacc[c];
        __syncthreads();

        int halfbase = base + hf * 128;
        int rv = E - halfbase; if (rv > 128) rv = 128;
        if (rv > 0) {
            int total = rv * PAIRS;
            for (int i = tid; i < total; i += 128) {
                int row = i / PAIRS, c2 = i - row * PAIRS;
                int ridx = hf * 128 + row;
                ull pv = *(const ull*)(g_P + (size_t)sS[ridx] * PPITCH + c2 * 2);
                ull qv = *(const ull*)(g_Q + (size_t)sD[ridx] * PPITCH + c2 * 2);
                ull o = add2(add2(pv, qv), sOut[i]);
                *(ull*)(out + (size_t)(halfbase + row) * NCLS + c2 * 2) = o;
            }
        }
    }
}

// --------------------------------------------------------------------------
extern "C" void kernel_launch(void* const* d_in, const int* in_sizes, int n_in,
                              void* d_out, int out_size)
{
    const float* h   = (const float*)d_in[0];
    const float* e   = (const float*)d_in[1];
    const void*  src = d_in[2];
    const void*  dst = d_in[3];
    const float* W   = (const float*)d_in[4];
    const float* b   = (const float*)d_in[5];

    int N = in_sizes[0] / DIM;   // 50000
    int E = in_sizes[1] / DIM;   // 500000
    if (N > NMAX) N = NMAX;

    cudaFuncSetAttribute(node_kernel, cudaFuncAttributeMaxDynamicSharedMemorySize, NODE_SMEM);
    cudaFuncSetAttribute(edge_kernel, cudaFuncAttributeMaxDynamicSharedMemorySize, EDGE_SMEM);

    node_kernel<<<(N + 127) / 128, 128, NODE_SMEM>>>(h, W, b, src, N, E);
    edge_kernel<<<(E + 255) / 256, 128, EDGE_SMEM>>>(e, src, dst, W, (float*)d_out, E);
}